// round 6
// baseline (speedup 1.0000x reference)
#include <cuda_runtime.h>
#include <math.h>

#define N_NODES 20000
#define N_EDGES 150000
#define FEAT    64
#define HEADS   8
#define N_RBF   20
#define CUTOFF  5.0f
#define NO      1024        // Q(512) + K(512) columns per node
#define NOUT    512         // per-table (HEADS*FEAT)
#define NBINS   8192

// Scratch (device globals; no cudaMalloc allowed)
__device__ float g_qk[(size_t)N_NODES * NO];        // ~82 MB : per-node Q|K
__device__ float g_dk[(size_t)(NBINS + 1) * NOUT];  // ~17 MB : dk(dist) table
__device__ float g_wt[FEAT * NO];                   // 256 KB : W transposed [f][o]

// ---------------------------------------------------------------------------
// Kernel A: build dk table. One block per distance bin; 512 threads = 8x64 (h,f).
// RBF features computed in double precision by 20 threads, broadcast via smem.
// ---------------------------------------------------------------------------
__global__ __launch_bounds__(512) void build_dk_table(
    const float* __restrict__ W_dk, const float* __restrict__ b_dk)
{
    __shared__ float ef[N_RBF];
    int row = blockIdx.x;                       // 0..NBINS
    if (threadIdx.x < N_RBF) {
        double d = (double)row * ((double)CUTOFF / (double)NBINS);
        if (d < 1e-8) d = 1e-8;                 // row 0 never used (dist >= 0.5)
        double n = (double)(threadIdx.x + 1);
        double s = sin(n * 3.141592653589793 * d / 5.0) / d;
        double env = 0.5 * (cos(3.141592653589793 * d / 5.0) + 1.0);
        if (d >= 5.0) env = 0.0;
        ef[threadIdx.x] = (float)(s * env);
    }
    __syncthreads();
    int o = threadIdx.x;                        // o = h*64+f
    float z = b_dk[o];
#pragma unroll
    for (int r = 0; r < N_RBF; r++)
        z = fmaf(ef[r], W_dk[o * N_RBF + r], z);
    float dk = z / (1.0f + expf(-z));           // silu
    g_dk[(size_t)row * NOUT + o] = dk;
}

// ---------------------------------------------------------------------------
// Kernel A2: transpose W_q / W_k into k-major combined layout g_wt[f][o].
// ---------------------------------------------------------------------------
__global__ __launch_bounds__(256) void transpose_w(
    const float* __restrict__ W_q, const float* __restrict__ W_k)
{
    int idx = blockIdx.x * 256 + threadIdx.x;   // over FEAT*NO = 65536
    if (idx >= FEAT * NO) return;
    int f = idx / NO;
    int o = idx % NO;
    g_wt[idx] = (o < NOUT) ? W_q[o * FEAT + f] : W_k[(o - NOUT) * FEAT + f];
}

// ---------------------------------------------------------------------------
// Kernel B: QK GEMM.  g_qk[n][o] = sum_f x[n][f] * g_wt[f][o] + bias[o]
// Tile: BM=64 nodes x BN=64 outputs, K=FEAT=64, 128 threads, 8x4 microtile.
// Xs is node-major with pad 65 (broadcast scalar reads, distinct banks),
// Ws is k-major (conflict-free float4 reads; no transpose needed thanks to g_wt).
// ---------------------------------------------------------------------------
#define BM 64
#define BN 64
#define XLD 65
__global__ __launch_bounds__(128) void qk_gemm(
    const float* __restrict__ x,
    const float* __restrict__ b_q, const float* __restrict__ b_k)
{
    __shared__ float Xs[BM * XLD];
    __shared__ float Ws[FEAT * BN];
    const int bm = blockIdx.x * BM;
    const int bo = blockIdx.y * BN;
    const int tid = threadIdx.x;

    // Load X tile: 64 rows x 16 float4, coalesced.
    for (int t = tid; t < BM * 16; t += 128) {
        int m = t >> 4, c = t & 15;
        float4 v = make_float4(0.f, 0.f, 0.f, 0.f);
        int node = bm + m;
        if (node < N_NODES)
            v = *(const float4*)(x + (size_t)node * FEAT + c * 4);
        float* p = &Xs[m * XLD + c * 4];
        p[0] = v.x; p[1] = v.y; p[2] = v.z; p[3] = v.w;
    }
    // Load W tile (already k-major in g_wt): conflict-free float4 STS.
    for (int t = tid; t < FEAT * 16; t += 128) {
        int k = t >> 4, c = t & 15;
        *(float4*)&Ws[k * BN + c * 4] =
            *(const float4*)(g_wt + (size_t)k * NO + bo + c * 4);
    }
    __syncthreads();

    const int to = tid & 15;        // output group: 4 outputs
    const int tm = tid >> 4;        // node group: 8 nodes
    float acc[8][4];
#pragma unroll
    for (int i = 0; i < 8; i++) { acc[i][0]=0.f; acc[i][1]=0.f; acc[i][2]=0.f; acc[i][3]=0.f; }

#pragma unroll 8
    for (int k = 0; k < FEAT; k++) {
        float4 w = *(const float4*)&Ws[k * BN + to * 4];
#pragma unroll
        for (int i = 0; i < 8; i++) {
            float xv = Xs[(tm * 8 + i) * XLD + k];
            acc[i][0] = fmaf(xv, w.x, acc[i][0]);
            acc[i][1] = fmaf(xv, w.y, acc[i][1]);
            acc[i][2] = fmaf(xv, w.z, acc[i][2]);
            acc[i][3] = fmaf(xv, w.w, acc[i][3]);
        }
    }

    const int o0 = bo + to * 4;     // BN=64 divides 512: block fully in Q or K
    float4 bias = (o0 < NOUT) ? *(const float4*)(b_q + o0)
                              : *(const float4*)(b_k + (o0 - NOUT));
#pragma unroll
    for (int i = 0; i < 8; i++) {
        int node = bm + tm * 8 + i;
        if (node < N_NODES) {
            float4 r = make_float4(acc[i][0] + bias.x, acc[i][1] + bias.y,
                                   acc[i][2] + bias.z, acc[i][3] + bias.w);
            *(float4*)(g_qk + (size_t)node * NO + o0) = r;
        }
    }
}

// ---------------------------------------------------------------------------
// Kernel C: one warp per edge. Gather Q[i], K[j] (float4, coalesced), lerp dk
// from the table, accumulate per-head dot, 16-lane butterfly reduce, silu, store.
// Lane l, j in 0..3: float4 index = l + 32j  ->  o = 4l + 128j + c
//   head(o) = 2j + (l >> 4); lanes 0-15 own even heads, 16-31 odd heads.
// ---------------------------------------------------------------------------
__global__ __launch_bounds__(256) void edge_kernel(
    const float* __restrict__ dist, const int* __restrict__ nbrs,
    float* __restrict__ out)
{
    int warp = (blockIdx.x * blockDim.x + threadIdx.x) >> 5;
    int lane = threadIdx.x & 31;
    if (warp >= N_EDGES) return;
    const int e = warp;

    float d = dist[e];
    int ni = nbrs[2 * e];
    int nj = nbrs[2 * e + 1];

    float t = d * ((float)NBINS / CUTOFF);
    int b = (int)t;
    if (b < 0) b = 0;
    if (b > NBINS - 1) b = NBINS - 1;
    float fr = t - (float)b;

    const float4* qp = (const float4*)(g_qk + (size_t)ni * NO);
    const float4* kp = (const float4*)(g_qk + (size_t)nj * NO + NOUT);
    const float4* d0 = (const float4*)(g_dk + (size_t)b * NOUT);
    const float4* d1 = d0 + (NOUT / 4);

    float acc[4] = {0.f, 0.f, 0.f, 0.f};
#pragma unroll
    for (int j = 0; j < 4; j++) {
        int i4 = lane + 32 * j;
        float4 q  = qp[i4];
        float4 kk = kp[i4];
        float4 a  = d0[i4];
        float4 bb = d1[i4];
        float dkx = fmaf(fr, bb.x - a.x, a.x);
        float dky = fmaf(fr, bb.y - a.y, a.y);
        float dkz = fmaf(fr, bb.z - a.z, a.z);
        float dkw = fmaf(fr, bb.w - a.w, a.w);
        float s = acc[j];
        s = fmaf(q.x * kk.x, dkx, s);
        s = fmaf(q.y * kk.y, dky, s);
        s = fmaf(q.z * kk.z, dkz, s);
        s = fmaf(q.w * kk.w, dkw, s);
        acc[j] = s;
    }

    // Butterfly reduce within each 16-lane half (heads stay within halves).
#pragma unroll
    for (int off = 8; off >= 1; off >>= 1) {
#pragma unroll
        for (int j = 0; j < 4; j++)
            acc[j] += __shfl_xor_sync(0xffffffffu, acc[j], off);
    }

    int half = lane >> 4;           // 0: even heads, 1: odd heads
    int c = lane & 15;
    if (c < 4) {
        int h = 2 * c + half;
        float v = acc[c];
        out[(size_t)e * HEADS + h] = v / (1.0f + expf(-v));   // silu
    }
}

// ---------------------------------------------------------------------------
// Launch. Inputs (metadata order): dist, nbrs, x_i, W_q, b_q, W_k, b_k, W_dk, b_dk
// ---------------------------------------------------------------------------
extern "C" void kernel_launch(void* const* d_in, const int* in_sizes, int n_in,
                              void* d_out, int out_size)
{
    const float* dist = (const float*)d_in[0];
    const int*   nbrs = (const int*)  d_in[1];
    const float* x_i  = (const float*)d_in[2];
    const float* W_q  = (const float*)d_in[3];
    const float* b_q  = (const float*)d_in[4];
    const float* W_k  = (const float*)d_in[5];
    const float* b_k  = (const float*)d_in[6];
    const float* W_dk = (const float*)d_in[7];
    const float* b_dk = (const float*)d_in[8];
    float* out = (float*)d_out;

    build_dk_table<<<NBINS + 1, 512>>>(W_dk, b_dk);
    transpose_w<<<(FEAT * NO + 255) / 256, 256>>>(W_q, W_k);
    qk_gemm<<<dim3((N_NODES + BM - 1) / BM, NO / BN), 128>>>(x_i, b_q, b_k);
    edge_kernel<<<(N_EDGES * 32 + 255) / 256, 256>>>(dist, nbrs, out);
}

// round 8
// speedup vs baseline: 1.1770x; 1.1770x over previous
#include <cuda_runtime.h>
#include <cuda_fp16.h>
#include <mma.h>
#include <math.h>

using namespace nvcuda;

#define N_NODES 20000
#define GM      20032       // nodes padded to 313*64 for guard-free wmma GEMM
#define N_EDGES 150000
#define FEAT    64
#define HEADS   8
#define N_RBF   20
#define CUTOFF  5.0f
#define NO      1024        // Q(512) + K(512) columns per node
#define NOUT    512         // per-table (HEADS*FEAT)
#define NBINS   8192

// Scratch (device globals; no cudaMalloc allowed)
__device__ __half g_xh [(size_t)GM * FEAT];           // 2.5 MB : x in fp16 (padded rows zero)
__device__ __half g_wth[FEAT * NO];                   // 128 KB : W transposed [f][o], fp16
__device__ __half g_qkh[(size_t)GM * NO];             // ~40 MB : per-node Q|K, fp16
__device__ __half g_dkh[(size_t)(NBINS + 1) * NOUT];  // ~8.4 MB : dk(dist) table, fp16

// ---------------------------------------------------------------------------
// Kernel A: build dk table (fp16 out). One block per bin; 512 threads (h,f).
// ---------------------------------------------------------------------------
__global__ __launch_bounds__(512) void build_dk_table(
    const float* __restrict__ W_dk, const float* __restrict__ b_dk)
{
    __shared__ float ef[N_RBF];
    int row = blockIdx.x;                       // 0..NBINS
    if (threadIdx.x < N_RBF) {
        double d = (double)row * ((double)CUTOFF / (double)NBINS);
        if (d < 1e-8) d = 1e-8;                 // row 0 never used (dist >= 0.5)
        double n = (double)(threadIdx.x + 1);
        double s = sin(n * 3.141592653589793 * d / 5.0) / d;
        double env = 0.5 * (cos(3.141592653589793 * d / 5.0) + 1.0);
        if (d >= 5.0) env = 0.0;
        ef[threadIdx.x] = (float)(s * env);
    }
    __syncthreads();
    int o = threadIdx.x;                        // o = h*64+f
    float z = b_dk[o];
#pragma unroll
    for (int r = 0; r < N_RBF; r++)
        z = fmaf(ef[r], W_dk[o * N_RBF + r], z);
    float dk = z / (1.0f + expf(-z));           // silu
    g_dkh[(size_t)row * NOUT + o] = __float2half(dk);
}

// ---------------------------------------------------------------------------
// Kernel A2: x (fp32, N_NODES rows) -> g_xh (fp16, GM rows, pad rows zeroed).
// ---------------------------------------------------------------------------
__global__ __launch_bounds__(256) void convert_x(const float* __restrict__ x)
{
    int idx = blockIdx.x * 256 + threadIdx.x;   // over GM*FEAT/2 half2 elements
    if (idx >= GM * FEAT / 2) return;
    int row = idx / (FEAT / 2);
    __half2 h = __floats2half2_rn(0.f, 0.f);
    if (row < N_NODES) {
        const float2 v = *(const float2*)(x + (size_t)2 * idx);
        h = __floats2half2_rn(v.x, v.y);
    }
    *((__half2*)g_xh + idx) = h;
}

// ---------------------------------------------------------------------------
// Kernel A3: transpose W_q / W_k into k-major fp16 g_wth[f][o].
// ---------------------------------------------------------------------------
__global__ __launch_bounds__(256) void transpose_w(
    const float* __restrict__ W_q, const float* __restrict__ W_k)
{
    int idx = blockIdx.x * 256 + threadIdx.x;   // over FEAT*NO = 65536
    if (idx >= FEAT * NO) return;
    int f = idx / NO;
    int o = idx % NO;
    float v = (o < NOUT) ? W_q[o * FEAT + f] : W_k[(o - NOUT) * FEAT + f];
    g_wth[idx] = __float2half(v);
}

// ---------------------------------------------------------------------------
// Kernel B: tensor-core GEMM.  g_qkh[n][o] = fp16( X[n][:] . Wt[:][o] + bias )
// Block tile 64(M) x 128(N), 8 warps in 2x4, each warp 32x32 (four 16x16 wmma
// frags), K = 64 in 4 steps. Guard-free: GM = 313*64, NO = 8*128.
// fp32 accumulate -> smem -> bias + fp16 convert, half2 stores.
// ---------------------------------------------------------------------------
__global__ __launch_bounds__(256) void qk_gemm_wmma(
    const float* __restrict__ b_q, const float* __restrict__ b_k)
{
    __shared__ float Cs[64 * 128];              // 32 KB
    const int warp = threadIdx.x >> 5;
    const int wm = warp >> 2;                   // 0..1
    const int wn = warp & 3;                    // 0..3
    const int bm = blockIdx.x * 64;
    const int bn = blockIdx.y * 128;

    wmma::fragment<wmma::accumulator, 16, 16, 16, float> acc[2][2];
#pragma unroll
    for (int i = 0; i < 2; i++)
#pragma unroll
        for (int j = 0; j < 2; j++)
            wmma::fill_fragment(acc[i][j], 0.0f);

#pragma unroll
    for (int k = 0; k < FEAT; k += 16) {
        wmma::fragment<wmma::matrix_a, 16, 16, 16, __half, wmma::row_major> a[2];
        wmma::fragment<wmma::matrix_b, 16, 16, 16, __half, wmma::row_major> b[2];
#pragma unroll
        for (int i = 0; i < 2; i++)
            wmma::load_matrix_sync(a[i],
                g_xh + (size_t)(bm + wm * 32 + i * 16) * FEAT + k, FEAT);
#pragma unroll
        for (int j = 0; j < 2; j++)
            wmma::load_matrix_sync(b[j],
                g_wth + (size_t)k * NO + bn + wn * 32 + j * 16, NO);
#pragma unroll
        for (int i = 0; i < 2; i++)
#pragma unroll
            for (int j = 0; j < 2; j++)
                wmma::mma_sync(acc[i][j], a[i], b[j], acc[i][j]);
    }

#pragma unroll
    for (int i = 0; i < 2; i++)
#pragma unroll
        for (int j = 0; j < 2; j++)
            wmma::store_matrix_sync(Cs + (wm * 32 + i * 16) * 128 + wn * 32 + j * 16,
                                    acc[i][j], 128, wmma::mem_row_major);
    __syncthreads();

    // bias + fp16 convert, half2 stores. 64 rows x 64 half2 columns.
    for (int t = threadIdx.x; t < 64 * 64; t += 256) {
        int r = t >> 6, c2 = t & 63;
        int o = bn + c2 * 2;                    // even; NOUT even -> no pair straddle
        float bx = (o     < NOUT) ? b_q[o]           : b_k[o - NOUT];
        float by = (o + 1 < NOUT) ? b_q[o + 1]       : b_k[o + 1 - NOUT];
        __half2 hv = __floats2half2_rn(Cs[r * 128 + c2 * 2] + bx,
                                       Cs[r * 128 + c2 * 2 + 1] + by);
        *((__half2*)(g_qkh + (size_t)(bm + r) * NO + o)) = hv;
    }
}

// ---------------------------------------------------------------------------
// Kernel C: one warp per edge, fp16 data. Lane l, chunk j in {0,1}:
//   uint4 index = 32j + l  -> halfs o = 256j + 8l .. +7, all in head 4j+(l>>3).
// 8-lane butterfly reduce; lanes l%8==0 hold heads {g, 4+g}, g = l>>3.
// ---------------------------------------------------------------------------
__device__ __forceinline__ float dot8(uint4 qu, uint4 ku, uint4 au, uint4 bu, float fr)
{
    const __half2* q2 = (const __half2*)&qu;
    const __half2* k2 = (const __half2*)&ku;
    const __half2* a2 = (const __half2*)&au;
    const __half2* b2 = (const __half2*)&bu;
    float s = 0.f;
#pragma unroll
    for (int i = 0; i < 4; i++) {
        float2 q = __half22float2(q2[i]);
        float2 k = __half22float2(k2[i]);
        float2 a = __half22float2(a2[i]);
        float2 b = __half22float2(b2[i]);
        float dkx = fmaf(fr, b.x - a.x, a.x);
        float dky = fmaf(fr, b.y - a.y, a.y);
        s = fmaf(q.x * k.x, dkx, s);
        s = fmaf(q.y * k.y, dky, s);
    }
    return s;
}

__global__ __launch_bounds__(256) void edge_kernel(
    const float* __restrict__ dist, const int* __restrict__ nbrs,
    float* __restrict__ out)
{
    int warp = (blockIdx.x * blockDim.x + threadIdx.x) >> 5;
    int lane = threadIdx.x & 31;
    if (warp >= N_EDGES) return;
    const int e = warp;

    float d = dist[e];
    int ni = nbrs[2 * e];
    int nj = nbrs[2 * e + 1];

    float t = d * ((float)NBINS / CUTOFF);
    int b = (int)t;
    if (b < 0) b = 0;
    if (b > NBINS - 1) b = NBINS - 1;
    float fr = t - (float)b;

    const uint4* qp = (const uint4*)(g_qkh + (size_t)ni * NO);
    const uint4* kp = (const uint4*)(g_qkh + (size_t)nj * NO + NOUT);
    const uint4* d0 = (const uint4*)(g_dkh + (size_t)b * NOUT);
    const uint4* d1 = (const uint4*)(g_dkh + (size_t)(b + 1) * NOUT);

    // chunk 0
    uint4 q0 = qp[lane],      k0 = kp[lane];
    uint4 a0 = d0[lane],      b0 = d1[lane];
    // chunk 1
    uint4 q1 = qp[32 + lane], k1 = kp[32 + lane];
    uint4 a1 = d0[32 + lane], b1 = d1[32 + lane];

    float acc0 = dot8(q0, k0, a0, b0, fr);
    float acc1 = dot8(q1, k1, a1, b1, fr);

    // Butterfly reduce within 8-lane groups (heads stay within groups).
#pragma unroll
    for (int off = 4; off >= 1; off >>= 1) {
        acc0 += __shfl_xor_sync(0xffffffffu, acc0, off);
        acc1 += __shfl_xor_sync(0xffffffffu, acc1, off);
    }

    if ((lane & 7) == 0) {
        int g = lane >> 3;                      // 0..3
        out[(size_t)e * HEADS + g]     = acc0 / (1.0f + expf(-acc0));  // heads 0..3
        out[(size_t)e * HEADS + 4 + g] = acc1 / (1.0f + expf(-acc1));  // heads 4..7
    }
}

// ---------------------------------------------------------------------------
// Launch. Inputs (metadata order): dist, nbrs, x_i, W_q, b_q, W_k, b_k, W_dk, b_dk
// ---------------------------------------------------------------------------
extern "C" void kernel_launch(void* const* d_in, const int* in_sizes, int n_in,
                              void* d_out, int out_size)
{
    const float* dist = (const float*)d_in[0];
    const int*   nbrs = (const int*)  d_in[1];
    const float* x_i  = (const float*)d_in[2];
    const float* W_q  = (const float*)d_in[3];
    const float* b_q  = (const float*)d_in[4];
    const float* W_k  = (const float*)d_in[5];
    const float* b_k  = (const float*)d_in[6];
    const float* W_dk = (const float*)d_in[7];
    const float* b_dk = (const float*)d_in[8];
    float* out = (float*)d_out;

    build_dk_table<<<NBINS + 1, 512>>>(W_dk, b_dk);
    convert_x<<<(GM * FEAT / 2 + 255) / 256, 256>>>(x_i);
    transpose_w<<<(FEAT * NO + 255) / 256, 256>>>(W_q, W_k);
    qk_gemm_wmma<<<dim3(GM / 64, NO / 128), 256>>>(b_q, b_k);
    edge_kernel<<<(N_EDGES * 32 + 255) / 256, 256>>>(dist, nbrs, out);
}

// round 12
// speedup vs baseline: 1.8610x; 1.5811x over previous
#include <cuda_runtime.h>
#include <cuda_fp16.h>
#include <mma.h>
#include <math.h>

using namespace nvcuda;

#define N_NODES 20000
#define GM      20096       // nodes padded to 157*128 for guard-free wmma epilogue
#define N_EDGES 150000
#define FEAT    64
#define HEADS   8
#define N_RBF   20
#define CUTOFF  5.0f
#define NO      1024        // Q(512) + K(512) columns per node
#define NOUT    512         // per-table (HEADS*FEAT)
#define NBINS   4096

// Scratch (device globals; no cudaMalloc allowed)
__device__ __half g_wth[FEAT * NO];                   // 128 KB : W transposed [f][o], fp16
__device__ __half g_qkh[(size_t)GM * NO];             // ~41 MB : per-node Q|K, fp16
__device__ __half g_dkh[(size_t)(NBINS + 1) * NOUT];  // ~4.2 MB : dk(dist) table, fp16

// ---------------------------------------------------------------------------
// Kernel A: build dk table (fp16 out), fp32 math (sinf/cosf err ~1e-7 is
// negligible vs fp16 storage err 2.4e-4). One block per bin; 512 threads (h,f).
// ---------------------------------------------------------------------------
__global__ __launch_bounds__(512) void build_dk_table(
    const float* __restrict__ W_dk, const float* __restrict__ b_dk)
{
    __shared__ float ef[N_RBF];
    int row = blockIdx.x;                       // 0..NBINS
    if (threadIdx.x < N_RBF) {
        float d = (float)row * (CUTOFF / (float)NBINS);
        if (row == 0) d = 1e-6f;                // row 0 never used (dist >= 0.5)
        float n = (float)(threadIdx.x + 1);
        float s = sinf(n * 3.14159265358979f * d / 5.0f) / d;
        float env = 0.5f * (cosf(3.14159265358979f * d / 5.0f) + 1.0f);
        if (d >= 5.0f) env = 0.0f;
        ef[threadIdx.x] = s * env;
    }
    __syncthreads();
    int o = threadIdx.x;                        // o = h*64+f
    float z = b_dk[o];
#pragma unroll
    for (int r = 0; r < N_RBF; r++)
        z = fmaf(ef[r], W_dk[o * N_RBF + r], z);
    float dk = z / (1.0f + expf(-z));           // silu
    g_dkh[(size_t)row * NOUT + o] = __float2half(dk);
}

// ---------------------------------------------------------------------------
// Kernel A2: transpose W_q / W_k into k-major fp16 g_wth[f][o].
// ---------------------------------------------------------------------------
__global__ __launch_bounds__(256) void transpose_w(
    const float* __restrict__ W_q, const float* __restrict__ W_k)
{
    int idx = blockIdx.x * 256 + threadIdx.x;   // over FEAT*NO = 65536
    if (idx >= FEAT * NO) return;
    int f = idx / NO;
    int o = idx % NO;
    float v = (o < NOUT) ? W_q[o * FEAT + f] : W_k[(o - NOUT) * FEAT + f];
    g_wth[idx] = __float2half(v);
}

// ---------------------------------------------------------------------------
// Kernel B: smem-staged tensor-core GEMM.
//   g_qkh[n][o] = fp16( X[n][:] . Wt[:][o] + bias[o] )
// Block tile 128(M) x 128(N), full K=64 slab in smem. 8 warps in 2x4; each warp
// owns 64x32 (4x2 wmma 16x16x16 frags, 4 K-steps). A is converted fp32->fp16
// inline while staging. Padded smem strides (72 / 136) keep fragment loads
// conflict-free. Cs is UNIONED over As/Bs (disjoint lifetimes, separated by
// __syncthreads) to stay under the 48KB static-smem limit: max(35840,32768)B.
// __align__(16): staging uses 128-bit STS/LDS; base must be 16B-aligned.
// ---------------------------------------------------------------------------
#define TM 128
#define TN 128
#define ALD (FEAT + 8)      // 72
#define BLD (TN + 8)        // 136
__global__ __launch_bounds__(256) void qk_gemm_wmma(
    const float* __restrict__ x,
    const float* __restrict__ b_q, const float* __restrict__ b_k)
{
    __shared__ __align__(16) union SmU {
        struct {
            __half As[TM * ALD];                // 18432 B
            __half Bs[FEAT * BLD];              // 17408 B
        } ab;
        float Cs[64 * TN];                      // 32768 B
    } sm;                                       // 35840 B total
    __half* As = sm.ab.As;
    __half* Bs = sm.ab.Bs;
    float*  Cs = sm.Cs;

    const int tid = threadIdx.x;
    const int warp = tid >> 5;
    const int wm = warp >> 2;                   // 0..1 : 64-row half
    const int wn = warp & 3;                    // 0..3 : 32-col slice
    const int bm = blockIdx.x * TM;
    const int bn = blockIdx.y * TN;

    // Stage A: 128 rows x 16 float4 of x, convert to fp16. 8 passes of 16 rows.
#pragma unroll
    for (int p = 0; p < 8; p++) {
        int r = (tid >> 4) + p * 16;
        int c = tid & 15;                       // float4 column
        int node = bm + r;
        float4 v = make_float4(0.f, 0.f, 0.f, 0.f);
        if (node < N_NODES)
            v = *(const float4*)(x + (size_t)node * FEAT + c * 4);
        __half2* dst = (__half2*)&As[r * ALD + c * 4];
        dst[0] = __floats2half2_rn(v.x, v.y);
        dst[1] = __floats2half2_rn(v.z, v.w);
    }
    // Stage B: 64 rows x 16 uint4 (8 halfs) of g_wth.
#pragma unroll
    for (int p = 0; p < 4; p++) {
        int idx = tid + p * 256;
        int r = idx >> 4;
        int c = idx & 15;
        *(uint4*)&Bs[r * BLD + c * 8] =
            *(const uint4*)(g_wth + (size_t)r * NO + bn + c * 8);
    }
    __syncthreads();

    wmma::fragment<wmma::accumulator, 16, 16, 16, float> acc[4][2];
#pragma unroll
    for (int i = 0; i < 4; i++)
#pragma unroll
        for (int j = 0; j < 2; j++)
            wmma::fill_fragment(acc[i][j], 0.0f);

#pragma unroll
    for (int k = 0; k < FEAT; k += 16) {
        wmma::fragment<wmma::matrix_a, 16, 16, 16, __half, wmma::row_major> a[4];
        wmma::fragment<wmma::matrix_b, 16, 16, 16, __half, wmma::row_major> b[2];
#pragma unroll
        for (int i = 0; i < 4; i++)
            wmma::load_matrix_sync(a[i], &As[(wm * 64 + i * 16) * ALD + k], ALD);
#pragma unroll
        for (int j = 0; j < 2; j++)
            wmma::load_matrix_sync(b[j], &Bs[k * BLD + wn * 32 + j * 16], BLD);
#pragma unroll
        for (int i = 0; i < 4; i++)
#pragma unroll
            for (int j = 0; j < 2; j++)
                wmma::mma_sync(acc[i][j], a[i], b[j], acc[i][j]);
    }

    // Epilogue in two 64-row waves through Cs (overwrites As/Bs after sync):
    // bias + fp16 convert, half2 out.
#pragma unroll
    for (int hv = 0; hv < 2; hv++) {
        __syncthreads();                        // all mma reads of As/Bs done
        if (wm == hv) {
#pragma unroll
            for (int i = 0; i < 4; i++)
#pragma unroll
                for (int j = 0; j < 2; j++)
                    wmma::store_matrix_sync(&Cs[(i * 16) * TN + wn * 32 + j * 16],
                                            acc[i][j], TN, wmma::mem_row_major);
        }
        __syncthreads();
        for (int t = tid; t < 64 * 64; t += 256) {
            int r = t >> 6, c2 = t & 63;
            int o = bn + c2 * 2;                // even; NOUT even -> no straddle
            float bx = (o     < NOUT) ? b_q[o]     : b_k[o - NOUT];
            float by = (o + 1 < NOUT) ? b_q[o + 1] : b_k[o + 1 - NOUT];
            float2 cv = *(const float2*)&Cs[r * TN + c2 * 2];
            __half2 outv = __floats2half2_rn(cv.x + bx, cv.y + by);
            *((__half2*)(g_qkh + (size_t)(bm + hv * 64 + r) * NO + o)) = outv;
        }
    }
}

// ---------------------------------------------------------------------------
// Kernel C: one warp per edge, fp16 data. Lane l, chunk j in {0,1}:
//   uint4 index = 32j + l  -> halfs o = 256j + 8l .. +7, all in head 4j+(l>>3).
// 8-lane butterfly reduce; lanes l%8==0 hold heads {g, 4+g}, g = l>>3.
// ---------------------------------------------------------------------------
__device__ __forceinline__ float dot8(uint4 qu, uint4 ku, uint4 au, uint4 bu, float fr)
{
    const __half2* q2 = (const __half2*)&qu;
    const __half2* k2 = (const __half2*)&ku;
    const __half2* a2 = (const __half2*)&au;
    const __half2* b2 = (const __half2*)&bu;
    float s = 0.f;
#pragma unroll
    for (int i = 0; i < 4; i++) {
        float2 q = __half22float2(q2[i]);
        float2 k = __half22float2(k2[i]);
        float2 a = __half22float2(a2[i]);
        float2 b = __half22float2(b2[i]);
        float dkx = fmaf(fr, b.x - a.x, a.x);
        float dky = fmaf(fr, b.y - a.y, a.y);
        s = fmaf(q.x * k.x, dkx, s);
        s = fmaf(q.y * k.y, dky, s);
    }
    return s;
}

__global__ __launch_bounds__(256) void edge_kernel(
    const float* __restrict__ dist, const int* __restrict__ nbrs,
    float* __restrict__ out)
{
    int warp = (blockIdx.x * blockDim.x + threadIdx.x) >> 5;
    int lane = threadIdx.x & 31;
    if (warp >= N_EDGES) return;
    const int e = warp;

    float d = dist[e];
    int ni = nbrs[2 * e];
    int nj = nbrs[2 * e + 1];

    float t = d * ((float)NBINS / CUTOFF);
    int b = (int)t;
    if (b < 0) b = 0;
    if (b > NBINS - 1) b = NBINS - 1;
    float fr = t - (float)b;

    const uint4* qp = (const uint4*)(g_qkh + (size_t)ni * NO);
    const uint4* kp = (const uint4*)(g_qkh + (size_t)nj * NO + NOUT);
    const uint4* d0 = (const uint4*)(g_dkh + (size_t)b * NOUT);
    const uint4* d1 = (const uint4*)(g_dkh + (size_t)(b + 1) * NOUT);

    uint4 q0 = qp[lane],      k0 = kp[lane];
    uint4 a0 = d0[lane],      b0 = d1[lane];
    uint4 q1 = qp[32 + lane], k1 = kp[32 + lane];
    uint4 a1 = d0[32 + lane], b1 = d1[32 + lane];

    float acc0 = dot8(q0, k0, a0, b0, fr);
    float acc1 = dot8(q1, k1, a1, b1, fr);

#pragma unroll
    for (int off = 4; off >= 1; off >>= 1) {
        acc0 += __shfl_xor_sync(0xffffffffu, acc0, off);
        acc1 += __shfl_xor_sync(0xffffffffu, acc1, off);
    }

    if ((lane & 7) == 0) {
        int g = lane >> 3;                      // 0..3
        out[(size_t)e * HEADS + g]     = acc0 / (1.0f + expf(-acc0));  // heads 0..3
        out[(size_t)e * HEADS + 4 + g] = acc1 / (1.0f + expf(-acc1));  // heads 4..7
    }
}

// ---------------------------------------------------------------------------
// Launch. Inputs (metadata order): dist, nbrs, x_i, W_q, b_q, W_k, b_k, W_dk, b_dk
// ---------------------------------------------------------------------------
extern "C" void kernel_launch(void* const* d_in, const int* in_sizes, int n_in,
                              void* d_out, int out_size)
{
    const float* dist = (const float*)d_in[0];
    const int*   nbrs = (const int*)  d_in[1];
    const float* x_i  = (const float*)d_in[2];
    const float* W_q  = (const float*)d_in[3];
    const float* b_q  = (const float*)d_in[4];
    const float* W_k  = (const float*)d_in[5];
    const float* b_k  = (const float*)d_in[6];
    const float* W_dk = (const float*)d_in[7];
    const float* b_dk = (const float*)d_in[8];
    float* out = (float*)d_out;

    build_dk_table<<<NBINS + 1, 512>>>(W_dk, b_dk);
    transpose_w<<<(FEAT * NO + 255) / 256, 256>>>(W_q, W_k);
    qk_gemm_wmma<<<dim3(GM / TM, NO / TN), 256>>>(x_i, b_q, b_k);
    edge_kernel<<<(N_EDGES * 32 + 255) / 256, 256>>>(dist, nbrs, out);
}